// round 1
// baseline (speedup 1.0000x reference)
#include <cuda_runtime.h>
#include <cuda_bf16.h>

// ---------------------------------------------------------------------------
// GQA: B=2, T=2048, C=1024, H=16 q-heads, KVH=4 kv-heads, D=64, causal, RoPE
// Scratch (no allocation allowed):
//   g_q: [B,H,T,D]  = 2*16*2048*64 = 4,194,304 f32
//   g_k: [B,KVH,T,D]= 2*4*2048*64  = 1,048,576 f32
//   g_v: same as g_k
//   g_y: [B,T,H*D]  = 4,194,304 f32
// ---------------------------------------------------------------------------

__device__ __align__(16) float g_q[4194304];
__device__ __align__(16) float g_k[1048576];
__device__ __align__(16) float g_v[1048576];
__device__ __align__(16) float g_y[4194304];

// ---------------------------------------------------------------------------
// Fused QKV GEMM: A = x [4096,1024], B = [Wq | Wk | Wv] (N = 1024+256+256 = 1536)
// 128x128 block tile, BK=16, 8x8 per thread, 256 threads.
// Epilogue scatters into g_q/g_k/g_v in [B,head,T,D] layout.
// Tile columns are 128-aligned, and 1024/1280 are multiples of 128, so each
// block tile lies entirely inside one of Wq/Wk/Wv.
// ---------------------------------------------------------------------------
__global__ void __launch_bounds__(256) qkv_gemm_kernel(
    const float* __restrict__ x,
    const float* __restrict__ Wq,
    const float* __restrict__ Wk,
    const float* __restrict__ Wv)
{
    const int K = 1024;
    __shared__ __align__(16) float As[16][128];
    __shared__ __align__(16) float Bs[16][128];

    int tid  = threadIdx.x;
    int brow = blockIdx.y * 128;
    int bcol = blockIdx.x * 128;

    const float* Bmat; int ldb; int bc0;
    if (bcol < 1024)      { Bmat = Wq; ldb = 1024; bc0 = bcol;        }
    else if (bcol < 1280) { Bmat = Wk; ldb = 256;  bc0 = bcol - 1024; }
    else                  { Bmat = Wv; ldb = 256;  bc0 = bcol - 1280; }

    int tr = (tid >> 4) << 3;   // 0..120
    int tc = (tid & 15) << 3;   // 0..120

    float acc[8][8];
    #pragma unroll
    for (int i = 0; i < 8; i++)
        #pragma unroll
        for (int j = 0; j < 8; j++) acc[i][j] = 0.f;

    for (int kb = 0; kb < K; kb += 16) {
        #pragma unroll
        for (int i = 0; i < 2; i++) {
            int f  = tid + i * 256;          // 0..511
            int ar = f >> 2, ac = (f & 3) << 2;
            float4 av = *(const float4*)(x + (brow + ar) * K + kb + ac);
            As[ac + 0][ar] = av.x;
            As[ac + 1][ar] = av.y;
            As[ac + 2][ar] = av.z;
            As[ac + 3][ar] = av.w;
            int br = f >> 5, bcc = (f & 31) << 2;
            *(float4*)&Bs[br][bcc] =
                *(const float4*)(Bmat + (kb + br) * ldb + bc0 + bcc);
        }
        __syncthreads();
        #pragma unroll
        for (int kk = 0; kk < 16; kk++) {
            float a[8], bb[8];
            *(float4*)&a[0]  = *(const float4*)&As[kk][tr];
            *(float4*)&a[4]  = *(const float4*)&As[kk][tr + 4];
            *(float4*)&bb[0] = *(const float4*)&Bs[kk][tc];
            *(float4*)&bb[4] = *(const float4*)&Bs[kk][tc + 4];
            #pragma unroll
            for (int i = 0; i < 8; i++)
                #pragma unroll
                for (int j = 0; j < 8; j++)
                    acc[i][j] += a[i] * bb[j];
        }
        __syncthreads();
    }

    // scatter epilogue
    #pragma unroll
    for (int i = 0; i < 8; i++) {
        int r = brow + tr + i;
        int b = r >> 11, t = r & 2047;
        #pragma unroll
        for (int j = 0; j < 8; j++) {
            int c = bcol + tc + j;
            float val = acc[i][j];
            if (c < 1024) {
                int h = c >> 6, d = c & 63;
                g_q[(((b * 16 + h) * 2048 + t) << 6) + d] = val;
            } else if (c < 1280) {
                int c2 = c - 1024; int h = c2 >> 6, d = c2 & 63;
                g_k[(((b * 4 + h) * 2048 + t) << 6) + d] = val;
            } else {
                int c2 = c - 1280; int h = c2 >> 6, d = c2 & 63;
                g_v[(((b * 4 + h) * 2048 + t) << 6) + d] = val;
            }
        }
    }
}

// ---------------------------------------------------------------------------
// In-place RoPE on g_q (which=0) or g_k (which=1).
// Layout [bh][t][64]; pairs (d, d+32), d in [0,32).
// out[d]    = x1*cos - x2*sin
// out[d+32] = x2*cos + x1*sin
// ---------------------------------------------------------------------------
__global__ void rope_kernel(const float* __restrict__ cosb,
                            const float* __restrict__ sinb,
                            int n, int which)
{
    int i = blockIdx.x * blockDim.x + threadIdx.x;
    if (i >= n) return;
    float* buf = which ? g_k : g_q;
    int d  = i & 31;
    int t  = (i >> 5) & 2047;
    int bh = i >> 16;               // 2048*32 = 65536 elems per (b,head)
    float* base = buf + ((bh * 2048 + t) << 6);
    float c = cosb[t * 32 + d];
    float s = sinb[t * 32 + d];
    float x1 = base[d], x2 = base[d + 32];
    base[d]      = x1 * c - x2 * s;
    base[d + 32] = x2 * c + x1 * s;
}

// ---------------------------------------------------------------------------
// Causal flash attention, fp32. One q-row per thread, 128 rows per CTA.
// K/V tiles of 64 rows staged in smem. Online softmax with branchy rescale.
// grid = (T/128, B*H), block = 128.
// ---------------------------------------------------------------------------
__global__ void __launch_bounds__(128) attn_kernel()
{
    __shared__ __align__(16) float ks[64 * 64];
    __shared__ __align__(16) float vs[64 * 64];

    int bh = blockIdx.y;           // 0..31
    int b  = bh >> 4, h = bh & 15;
    int kh = h >> 2;               // jnp.repeat(k, 4, axis=1) -> kv head = h/4
    int tq = blockIdx.x * 128 + threadIdx.x;

    // q row, scale 1/sqrt(64) folded in
    float qr[64];
    const float4* qrow = (const float4*)(g_q + ((bh * 2048 + tq) << 6));
    #pragma unroll
    for (int i = 0; i < 16; i++) {
        float4 t4 = qrow[i];
        qr[i*4+0] = t4.x * 0.125f; qr[i*4+1] = t4.y * 0.125f;
        qr[i*4+2] = t4.z * 0.125f; qr[i*4+3] = t4.w * 0.125f;
    }
    float o[64];
    #pragma unroll
    for (int i = 0; i < 64; i++) o[i] = 0.f;
    float m = -1e30f, l = 0.f;

    const float* kbase = g_k + (((b * 4 + kh) * 2048) << 6);
    const float* vbase = g_v + (((b * 4 + kh) * 2048) << 6);

    int ntiles = blockIdx.x * 2 + 2;           // causal: tiles 0..(row0+128)/64
    for (int kt = 0; kt < ntiles; kt++) {
        const float4* ksrc = (const float4*)(kbase + kt * 64 * 64);
        const float4* vsrc = (const float4*)(vbase + kt * 64 * 64);
        #pragma unroll
        for (int i = 0; i < 8; i++) {
            int f = threadIdx.x + i * 128;     // 0..1023 float4s
            ((float4*)ks)[f] = ksrc[f];
            ((float4*)vs)[f] = vsrc[f];
        }
        __syncthreads();

        int jmax = tq - kt * 64 + 1;
        if (jmax > 64) jmax = 64;
        for (int j = 0; j < jmax; j++) {
            const float4* krow = (const float4*)(ks + j * 64);
            float s0 = 0.f, s1 = 0.f, s2 = 0.f, s3 = 0.f;   // break FMA chain
            #pragma unroll
            for (int d4 = 0; d4 < 16; d4++) {
                float4 k4 = krow[d4];
                s0 += qr[d4*4+0] * k4.x;
                s1 += qr[d4*4+1] * k4.y;
                s2 += qr[d4*4+2] * k4.z;
                s3 += qr[d4*4+3] * k4.w;
            }
            float s = (s0 + s1) + (s2 + s3);
            const float4* vrow = (const float4*)(vs + j * 64);
            if (s <= m) {
                float p = __expf(s - m);
                l += p;
                #pragma unroll
                for (int d4 = 0; d4 < 16; d4++) {
                    float4 v4 = vrow[d4];
                    o[d4*4+0] += p * v4.x; o[d4*4+1] += p * v4.y;
                    o[d4*4+2] += p * v4.z; o[d4*4+3] += p * v4.w;
                }
            } else {
                float corr = __expf(m - s);
                m = s;
                l = l * corr + 1.f;
                #pragma unroll
                for (int d4 = 0; d4 < 16; d4++) {
                    float4 v4 = vrow[d4];
                    o[d4*4+0] = o[d4*4+0] * corr + v4.x;
                    o[d4*4+1] = o[d4*4+1] * corr + v4.y;
                    o[d4*4+2] = o[d4*4+2] * corr + v4.z;
                    o[d4*4+3] = o[d4*4+3] * corr + v4.w;
                }
            }
        }
        __syncthreads();
    }

    float inv = 1.f / l;
    float4* yrow = (float4*)(g_y + (b * 2048 + tq) * 1024 + h * 64);
    #pragma unroll
    for (int i = 0; i < 16; i++) {
        float4 t4;
        t4.x = o[i*4+0] * inv; t4.y = o[i*4+1] * inv;
        t4.z = o[i*4+2] * inv; t4.w = o[i*4+3] * inv;
        yrow[i] = t4;
    }
}

// ---------------------------------------------------------------------------
// Output projection: C[4096,1024] = g_y[4096,1024] @ Wo[1024,1024]
// Same tiling as qkv_gemm.
// ---------------------------------------------------------------------------
__global__ void __launch_bounds__(256) wo_gemm_kernel(
    const float* __restrict__ Wo, float* __restrict__ C)
{
    const int K = 1024, N = 1024;
    __shared__ __align__(16) float As[16][128];
    __shared__ __align__(16) float Bs[16][128];

    int tid  = threadIdx.x;
    int brow = blockIdx.y * 128;
    int bcol = blockIdx.x * 128;

    int tr = (tid >> 4) << 3;
    int tc = (tid & 15) << 3;

    float acc[8][8];
    #pragma unroll
    for (int i = 0; i < 8; i++)
        #pragma unroll
        for (int j = 0; j < 8; j++) acc[i][j] = 0.f;

    for (int kb = 0; kb < K; kb += 16) {
        #pragma unroll
        for (int i = 0; i < 2; i++) {
            int f  = tid + i * 256;
            int ar = f >> 2, ac = (f & 3) << 2;
            float4 av = *(const float4*)(g_y + (brow + ar) * K + kb + ac);
            As[ac + 0][ar] = av.x;
            As[ac + 1][ar] = av.y;
            As[ac + 2][ar] = av.z;
            As[ac + 3][ar] = av.w;
            int br = f >> 5, bcc = (f & 31) << 2;
            *(float4*)&Bs[br][bcc] =
                *(const float4*)(Wo + (kb + br) * N + bcol + bcc);
        }
        __syncthreads();
        #pragma unroll
        for (int kk = 0; kk < 16; kk++) {
            float a[8], bb[8];
            *(float4*)&a[0]  = *(const float4*)&As[kk][tr];
            *(float4*)&a[4]  = *(const float4*)&As[kk][tr + 4];
            *(float4*)&bb[0] = *(const float4*)&Bs[kk][tc];
            *(float4*)&bb[4] = *(const float4*)&Bs[kk][tc + 4];
            #pragma unroll
            for (int i = 0; i < 8; i++)
                #pragma unroll
                for (int j = 0; j < 8; j++)
                    acc[i][j] += a[i] * bb[j];
        }
        __syncthreads();
    }

    #pragma unroll
    for (int i = 0; i < 8; i++) {
        int r = brow + tr + i;
        #pragma unroll
        for (int j = 0; j < 8; j += 4) {
            float4 t4;
            t4.x = acc[i][j+0]; t4.y = acc[i][j+1];
            t4.z = acc[i][j+2]; t4.w = acc[i][j+3];
            *(float4*)&C[r * N + bcol + tc + j] = t4;
        }
    }
}

// ---------------------------------------------------------------------------
// Launch: x, cos, sin, Wq, Wk, Wv, Wo  (metadata order). out = f32 [B,T,C].
// ---------------------------------------------------------------------------
extern "C" void kernel_launch(void* const* d_in, const int* in_sizes, int n_in,
                              void* d_out, int out_size)
{
    const float* x    = (const float*)d_in[0];
    const float* cosb = (const float*)d_in[1];
    const float* sinb = (const float*)d_in[2];
    const float* Wq   = (const float*)d_in[3];
    const float* Wk   = (const float*)d_in[4];
    const float* Wv   = (const float*)d_in[5];
    const float* Wo   = (const float*)d_in[6];
    float* out = (float*)d_out;

    // 1. fused QKV projection  (N tiles: 12 = 1536/128, M tiles: 32 = 4096/128)
    qkv_gemm_kernel<<<dim3(12, 32), 256>>>(x, Wq, Wk, Wv);

    // 2. RoPE on q: 2*16*2048*32 = 2,097,152 threads
    rope_kernel<<<8192, 256>>>(cosb, sinb, 2097152, 0);
    // 3. RoPE on k: 2*4*2048*32 = 524,288 threads
    rope_kernel<<<2048, 256>>>(cosb, sinb, 524288, 1);

    // 4. causal attention  (T/128 = 16 q-tiles, B*H = 32)
    attn_kernel<<<dim3(16, 32), 128>>>();

    // 5. output projection  (N tiles: 8, M tiles: 32)
    wo_gemm_kernel<<<dim3(8, 32), 256>>>(Wo, out);
}